// round 3
// baseline (speedup 1.0000x reference)
#include <cuda_runtime.h>
#include <stdint.h>

// CornerActivationB: out[b, g*16+d] = bilinear interp of params[g, 0..3, d]
//   u_i = (clip(x_i,-1,1)+1)*0.5
//   out = (1-u0)(1-u1)P0 + (1-u0)u1 P1 + u0(1-u1)P2 + u0 u1 P3
//
// BATCH=8192, GROUPS=512, OUT_DIM=16.
// X: [8192,1024] f32 (read-once), params: [512,4,16] f32 (register-resident),
// out: [8192,8192] f32 (write-once -> streaming stores).
//
// 256 thr/block: tid -> (g_local = tid>>2, quad q = tid&3). Each thread holds
// its 4 param float4s in registers, loops 32 batch rows, unroll 8 for MLP.

#define GROUPS   512
#define OUT_DIM  16
#define BATCH    8192
#define GDIM     (GROUPS * OUT_DIM)   // 8192
#define XDIM     (GROUPS * 2)         // 1024
#define G_TILE   64
#define B_TILE   32

__global__ void __launch_bounds__(256, 4)
corner_act_kernel(const float* __restrict__ X,
                  const float* __restrict__ P,
                  float* __restrict__ out)
{
    const int tid   = threadIdx.x;
    const int q     = tid & 3;
    const int gl    = tid >> 2;
    const int gtile = blockIdx.x & (GROUPS / G_TILE - 1);   // 0..7
    const int btile = blockIdx.x >> 3;                       // 0..255
    const int g     = gtile * G_TILE + gl;
    const int b0    = btile * B_TILE;

    const float4* Pg = reinterpret_cast<const float4*>(P) + (size_t)g * 16;
    const float4 p0 = Pg[0 * 4 + q];
    const float4 p1 = Pg[1 * 4 + q];
    const float4 p2 = Pg[2 * 4 + q];
    const float4 p3 = Pg[3 * 4 + q];

    const float2* Xb = reinterpret_cast<const float2*>(X + (size_t)b0 * XDIM) + g;
    float*        Ob = out + (size_t)b0 * GDIM + (size_t)g * OUT_DIM + q * 4;

    #pragma unroll 8
    for (int r = 0; r < B_TILE; ++r) {
        // read-once input: evict-first
        float2 xv = __ldcs(Xb + (size_t)r * (XDIM / 2));
        float u0 = (fminf(fmaxf(xv.x, -1.0f), 1.0f) + 1.0f) * 0.5f;
        float u1 = (fminf(fmaxf(xv.y, -1.0f), 1.0f) + 1.0f) * 0.5f;
        float v0 = 1.0f - u0;
        float v1 = 1.0f - u1;
        float c00 = v0 * v1;
        float c01 = v0 * u1;
        float c10 = u0 * v1;
        float c11 = u0 * u1;

        float4 o;
        o.x = c00 * p0.x + c01 * p1.x + c10 * p2.x + c11 * p3.x;
        o.y = c00 * p0.y + c01 * p1.y + c10 * p2.y + c11 * p3.y;
        o.z = c00 * p0.z + c01 * p1.z + c10 * p2.z + c11 * p3.z;
        o.w = c00 * p0.w + c01 * p1.w + c10 * p2.w + c11 * p3.w;

        // write-once output: streaming store (evict-first, don't pollute L2)
        __stcs(reinterpret_cast<float4*>(Ob + (size_t)r * GDIM), o);
    }
}

extern "C" void kernel_launch(void* const* d_in, const int* in_sizes, int n_in,
                              void* d_out, int out_size)
{
    const float* X = (const float*)d_in[0];
    const float* P = (const float*)d_in[1];
    float* out = (float*)d_out;

    dim3 grid((GROUPS / G_TILE) * (BATCH / B_TILE));  // 2048 blocks
    dim3 block(256);
    corner_act_kernel<<<grid, block>>>(X, P, out);
}

// round 4
// speedup vs baseline: 1.4624x; 1.4624x over previous
#include <cuda_runtime.h>
#include <stdint.h>

// CornerActivationB: out[b, g*16+d] = bilinear interp of params[g, 0..3, d]
//   u_i = (clip(x_i,-1,1)+1)*0.5
//   out = (1-u0)(1-u1)P0 + (1-u0)u1 P1 + u0(1-u1)P2 + u0 u1 P3
//
// BATCH=8192, GROUPS=512, OUT_DIM=16.
// X: [8192,1024] f32, params: [512,4,16] f32, out: [8192,8192] f32.
//
// R4 layout: 256 thr/block -> (g_local = tid>>3 in [0,32), pair = tid&7
// covering d in [2*pair, 2*pair+2)). Each thread keeps only 4 param float2s
// (8 regs) so the kernel fits ~40 regs -> 6 blocks/SM (75% occ) for more
// outstanding-store concurrency. Plain LDG/STG (streaming hints regressed R3).

#define GROUPS   512
#define OUT_DIM  16
#define BATCH    8192
#define GDIM     (GROUPS * OUT_DIM)   // 8192
#define XDIM     (GROUPS * 2)         // 1024
#define G_TILE   32
#define B_TILE   32

__global__ void __launch_bounds__(256, 6)
corner_act_kernel(const float* __restrict__ X,
                  const float* __restrict__ P,
                  float* __restrict__ out)
{
    const int tid   = threadIdx.x;
    const int pr    = tid & 7;           // d-pair (0..7), d = 2*pr..2*pr+1
    const int gl    = tid >> 3;          // group within tile (0..31)
    const int gtile = blockIdx.x & (GROUPS / G_TILE - 1);   // 0..15
    const int btile = blockIdx.x >> 4;                       // 0..255
    const int g     = gtile * G_TILE + gl;
    const int b0    = btile * B_TILE;

    // params[g, j, d]: float2 index = g*32 + j*8 + pr
    const float2* Pg = reinterpret_cast<const float2*>(P) + (size_t)g * 32;
    const float2 p0 = Pg[0 * 8 + pr];
    const float2 p1 = Pg[1 * 8 + pr];
    const float2 p2 = Pg[2 * 8 + pr];
    const float2 p3 = Pg[3 * 8 + pr];

    const float2* Xb = reinterpret_cast<const float2*>(X + (size_t)b0 * XDIM) + g;
    float*        Ob = out + (size_t)b0 * GDIM + (size_t)g * OUT_DIM + pr * 2;

    #pragma unroll 4
    for (int r = 0; r < B_TILE; ++r) {
        float2 xv = __ldg(Xb + (size_t)r * (XDIM / 2));   // 8-way lane broadcast
        float u0 = (fminf(fmaxf(xv.x, -1.0f), 1.0f) + 1.0f) * 0.5f;
        float u1 = (fminf(fmaxf(xv.y, -1.0f), 1.0f) + 1.0f) * 0.5f;
        float v0 = 1.0f - u0;
        float v1 = 1.0f - u1;
        float c00 = v0 * v1;
        float c01 = v0 * u1;
        float c10 = u0 * v1;
        float c11 = u0 * u1;

        float2 o;
        o.x = c00 * p0.x + c01 * p1.x + c10 * p2.x + c11 * p3.x;
        o.y = c00 * p0.y + c01 * p1.y + c10 * p2.y + c11 * p3.y;

        *reinterpret_cast<float2*>(Ob + (size_t)r * GDIM) = o;
    }
}

extern "C" void kernel_launch(void* const* d_in, const int* in_sizes, int n_in,
                              void* d_out, int out_size)
{
    const float* X = (const float*)d_in[0];
    const float* P = (const float*)d_in[1];
    float* out = (float*)d_out;

    dim3 grid((GROUPS / G_TILE) * (BATCH / B_TILE));  // 16 * 256 = 4096 blocks
    dim3 block(256);
    corner_act_kernel<<<grid, block>>>(X, P, out);
}

// round 5
// speedup vs baseline: 1.5559x; 1.0639x over previous
#include <cuda_runtime.h>
#include <stdint.h>

// CornerActivationB: out[b, g*16+d] = bilinear interp of params[g, 0..3, d]
//   u_i = (clip(x_i,-1,1)+1)*0.5
//   out = (1-u0)(1-u1)P0 + (1-u0)u1 P1 + u0(1-u1)P2 + u0 u1 P3
//
// BATCH=8192, GROUPS=512, OUT_DIM=16.
// X: [8192,1024] f32, params: [512,4,16] f32, out: [8192,8192] f32.
//
// R5: R2's float4/STG.128 layout (widest stores, 512B/warp contiguous) +
// register cap for 5 blocks/SM (40 warps, 62.5% occ). Evidence: R2 (wide
// stores, occ 44%) and R4 (narrow stores, occ 67%) both plateau at ~58% DRAM;
// this combines width AND concurrency.

#define GROUPS   512
#define OUT_DIM  16
#define BATCH    8192
#define GDIM     (GROUPS * OUT_DIM)   // 8192
#define XDIM     (GROUPS * 2)         // 1024
#define G_TILE   64
#define B_TILE   32

__global__ void __launch_bounds__(256, 5)
corner_act_kernel(const float* __restrict__ X,
                  const float* __restrict__ P,
                  float* __restrict__ out)
{
    const int tid   = threadIdx.x;
    const int q     = tid & 3;           // d-quad (0..3)
    const int gl    = tid >> 2;          // group within tile (0..63)
    const int gtile = blockIdx.x & (GROUPS / G_TILE - 1);   // 0..7
    const int btile = blockIdx.x >> 3;                       // 0..255
    const int g     = gtile * G_TILE + gl;
    const int b0    = btile * B_TILE;

    // params[g, j, d]: float4 index g*16 + j*4 + q
    const float4* Pg = reinterpret_cast<const float4*>(P) + (size_t)g * 16;
    const float4 p0 = Pg[0 * 4 + q];
    const float4 p1 = Pg[1 * 4 + q];
    const float4 p2 = Pg[2 * 4 + q];
    const float4 p3 = Pg[3 * 4 + q];

    const float2* Xb = reinterpret_cast<const float2*>(X + (size_t)b0 * XDIM) + g;
    float*        Ob = out + (size_t)b0 * GDIM + (size_t)g * OUT_DIM + q * 4;

    #pragma unroll 4
    for (int r = 0; r < B_TILE; ++r) {
        float2 xv = __ldg(Xb + (size_t)r * (XDIM / 2));   // 4-way lane broadcast
        float u0 = (fminf(fmaxf(xv.x, -1.0f), 1.0f) + 1.0f) * 0.5f;
        float u1 = (fminf(fmaxf(xv.y, -1.0f), 1.0f) + 1.0f) * 0.5f;
        float v0 = 1.0f - u0;
        float v1 = 1.0f - u1;
        float c00 = v0 * v1;
        float c01 = v0 * u1;
        float c10 = u0 * v1;
        float c11 = u0 * u1;

        float4 o;
        o.x = c00 * p0.x + c01 * p1.x + c10 * p2.x + c11 * p3.x;
        o.y = c00 * p0.y + c01 * p1.y + c10 * p2.y + c11 * p3.y;
        o.z = c00 * p0.z + c01 * p1.z + c10 * p2.z + c11 * p3.z;
        o.w = c00 * p0.w + c01 * p1.w + c10 * p2.w + c11 * p3.w;

        *reinterpret_cast<float4*>(Ob + (size_t)r * GDIM) = o;
    }
}

extern "C" void kernel_launch(void* const* d_in, const int* in_sizes, int n_in,
                              void* d_out, int out_size)
{
    const float* X = (const float*)d_in[0];
    const float* P = (const float*)d_in[1];
    float* out = (float*)d_out;

    dim3 grid((GROUPS / G_TILE) * (BATCH / B_TILE));  // 8 * 256 = 2048 blocks
    dim3 block(256);
    corner_act_kernel<<<grid, block>>>(X, P, out);
}

// round 6
// speedup vs baseline: 1.5631x; 1.0046x over previous
#include <cuda_runtime.h>
#include <stdint.h>

// CornerActivationB: out[b, g*16+d] = bilinear interp of params[g, 0..3, d]
//   u_i = (clip(x_i,-1,1)+1)*0.5
//   out = (1-u0)(1-u1)P0 + (1-u0)u1 P1 + u0(1-u1)P2 + u0 u1 P3
//
// BATCH=8192, GROUPS=512, OUT_DIM=16.
// X: [8192,1024] f32, params: [512,4,16] f32, out: [8192,8192] f32.
//
// R6: single-wave persistent kernel. Evidence from R2/R4/R5: DRAM pinned at
// 57-59% regardless of occ/store width; measured occ (54.6%) < theoretical
// (62.5%) exposes a wave-quantization tail (2048 blocks / 740 resident = 2.77
// waves). Fix: grid = 8 gtiles x 92 = 736 blocks = exactly one wave at
// 5 blocks/SM; each block strides over 4-row btiles (22-23 iters, ~3% skew).
// Params load once per block; stores stay 512B/warp contiguous STG.128.

#define GROUPS    512
#define OUT_DIM   16
#define BATCH     8192
#define GDIM      (GROUPS * OUT_DIM)   // 8192
#define XDIM      (GROUPS * 2)         // 1024
#define G_TILE    64
#define B_TILE    4
#define NBT       (BATCH / B_TILE)     // 2048 btiles per gtile
#define NCHUNK    92                   // blocks per gtile; 8*92=736 = 148 SMs * 5 - 4

__global__ void __launch_bounds__(256, 5)
corner_act_kernel(const float* __restrict__ X,
                  const float* __restrict__ P,
                  float* __restrict__ out)
{
    const int tid   = threadIdx.x;
    const int q     = tid & 3;           // d-quad (0..3)
    const int gl    = tid >> 2;          // group within tile (0..63)
    const int gtile = blockIdx.x & 7;    // 0..7
    const int chunk = blockIdx.x >> 3;   // 0..91
    const int g     = gtile * G_TILE + gl;

    // params[g, j, d]: float4 index g*16 + j*4 + q  (loaded once per block)
    const float4* Pg = reinterpret_cast<const float4*>(P) + (size_t)g * 16;
    const float4 p0 = Pg[0 * 4 + q];
    const float4 p1 = Pg[1 * 4 + q];
    const float4 p2 = Pg[2 * 4 + q];
    const float4 p3 = Pg[3 * 4 + q];

    const float2* X2 = reinterpret_cast<const float2*>(X) + g;   // + b*512
    float*        O  = out + (size_t)g * OUT_DIM + q * 4;        // + b*8192

    for (int bt = chunk; bt < NBT; bt += NCHUNK) {
        const int b0 = bt * B_TILE;
        const float2* Xp = X2 + (size_t)b0 * (XDIM / 2);
        float*        Op = O  + (size_t)b0 * GDIM;

        #pragma unroll
        for (int r = 0; r < B_TILE; ++r) {
            float2 xv = __ldg(Xp + (size_t)r * (XDIM / 2));  // 4-way broadcast
            float u0 = (fminf(fmaxf(xv.x, -1.0f), 1.0f) + 1.0f) * 0.5f;
            float u1 = (fminf(fmaxf(xv.y, -1.0f), 1.0f) + 1.0f) * 0.5f;
            float v0 = 1.0f - u0;
            float v1 = 1.0f - u1;
            float c00 = v0 * v1;
            float c01 = v0 * u1;
            float c10 = u0 * v1;
            float c11 = u0 * u1;

            float4 o;
            o.x = c00 * p0.x + c01 * p1.x + c10 * p2.x + c11 * p3.x;
            o.y = c00 * p0.y + c01 * p1.y + c10 * p2.y + c11 * p3.y;
            o.z = c00 * p0.z + c01 * p1.z + c10 * p2.z + c11 * p3.z;
            o.w = c00 * p0.w + c01 * p1.w + c10 * p2.w + c11 * p3.w;

            *reinterpret_cast<float4*>(Op + (size_t)r * GDIM) = o;
        }
    }
}

extern "C" void kernel_launch(void* const* d_in, const int* in_sizes, int n_in,
                              void* d_out, int out_size)
{
    const float* X = (const float*)d_in[0];
    const float* P = (const float*)d_in[1];
    float* out = (float*)d_out;

    dim3 grid(8 * NCHUNK);   // 736 blocks = one wave at 5 blocks/SM
    dim3 block(256);
    corner_act_kernel<<<grid, block>>>(X, P, out);
}